// round 8
// baseline (speedup 1.0000x reference)
#include <cuda_runtime.h>
#include <cuda_bf16.h>
#include <cstdint>
#include <math.h>

// ---------------- problem constants ----------------
#define T_STEPS 512
#define B_SZ    64
#define D_SZ    512
#define H_SZ    1024
#define G4      4096          // 4*H
#define BH      (B_SZ*H_SZ)   // 65536
#define NCTA    128

// ---------------- global scratch / sync state ----------------
__device__ float g_xg[(size_t)T_STEPS * B_SZ * G4];   // 512 MB, Xg = X@Wx + b
__device__ __nv_bfloat16 g_Hh[2][BH];                 // H split-bf16 hi, ping-pong
__device__ __nv_bfloat16 g_Hl[2][BH];                 // H split-bf16 lo
__device__ __nv_bfloat16 g_Xh[(size_t)T_STEPS * B_SZ * D_SZ];   // X split hi
__device__ __nv_bfloat16 g_Xl[(size_t)T_STEPS * B_SZ * D_SZ];   // X split lo
__device__ __nv_bfloat16 g_Wxh[(size_t)D_SZ * G4];    // Wx concat split hi
__device__ __nv_bfloat16 g_Wxl[(size_t)D_SZ * G4];    // Wx concat split lo
__device__ float g_bcat[G4];                          // bias concat
__device__ int      g_ready[NCTA];                    // per-CTA step counter
__device__ unsigned g_arrive = 0;
__device__ unsigned g_gen    = 0;

// ---------------- helpers ----------------
__device__ __forceinline__ uint32_t smem_u32(const void* p) {
    uint32_t a;
    asm("{ .reg .u64 t; cvta.to.shared.u64 t, %1; cvt.u32.u64 %0, t; }" : "=r"(a) : "l"(p));
    return a;
}
__device__ __forceinline__ void ldsm_x4(uint32_t* r, uint32_t addr) {
    asm volatile("ldmatrix.sync.aligned.m8n8.x4.shared.b16 {%0,%1,%2,%3}, [%4];"
                 : "=r"(r[0]), "=r"(r[1]), "=r"(r[2]), "=r"(r[3]) : "r"(addr));
}
__device__ __forceinline__ void ldsm_x4t(uint32_t* r, uint32_t addr) {
    asm volatile("ldmatrix.sync.aligned.m8n8.x4.trans.shared.b16 {%0,%1,%2,%3}, [%4];"
                 : "=r"(r[0]), "=r"(r[1]), "=r"(r[2]), "=r"(r[3]) : "r"(addr));
}
__device__ __forceinline__ void mma16816(float* c, const uint32_t* a, uint32_t b0, uint32_t b1) {
    asm volatile(
        "mma.sync.aligned.m16n8k16.row.col.f32.bf16.bf16.f32 "
        "{%0,%1,%2,%3}, {%4,%5,%6,%7}, {%8,%9}, {%0,%1,%2,%3};"
        : "+f"(c[0]), "+f"(c[1]), "+f"(c[2]), "+f"(c[3])
        : "r"(a[0]), "r"(a[1]), "r"(a[2]), "r"(a[3]), "r"(b0), "r"(b1));
}
__device__ __forceinline__ void cp16(uint32_t saddr, const void* g) {
    asm volatile("cp.async.cg.shared.global [%0], [%1], 16;" :: "r"(saddr), "l"(g));
}
#define CP_COMMIT() asm volatile("cp.async.commit_group;" ::: "memory")
#define CP_WAIT(N)  asm volatile("cp.async.wait_group %0;" :: "n"(N) : "memory")

__device__ __forceinline__ void wait_ready(int idx, int target) {
    int v;
    do {
        asm volatile("ld.acquire.gpu.s32 %0, [%1];" : "=r"(v) : "l"(g_ready + idx) : "memory");
        if (v < target) __nanosleep(32);
    } while (v < target);
}

// self-resetting generation barrier (replay-safe)
__device__ __forceinline__ void init_barrier() {
    __syncthreads();
    if (threadIdx.x == 0) {
        __threadfence();
        unsigned gen;
        asm volatile("ld.acquire.gpu.u32 %0, [%1];" : "=r"(gen) : "l"(&g_gen) : "memory");
        unsigned old = atomicAdd(&g_arrive, 1u);
        if (old == NCTA - 1) {
            atomicExch(&g_arrive, 0u);
            __threadfence();
            atomicAdd(&g_gen, 1u);
        } else {
            unsigned cur;
            do {
                __nanosleep(64);
                asm volatile("ld.acquire.gpu.u32 %0, [%1];" : "=r"(cur) : "l"(&g_gen) : "memory");
            } while (cur == gen);
        }
        __threadfence();
    }
    __syncthreads();
}

__device__ __forceinline__ void split2u(float v, unsigned& h, unsigned& l) {
    __nv_bfloat16 hb = __float2bfloat16(v);
    float r = v - __bfloat162float(hb);
    __nv_bfloat16 lb = __float2bfloat16(r);
    h = (unsigned)*reinterpret_cast<unsigned short*>(&hb);
    l = (unsigned)*reinterpret_cast<unsigned short*>(&lb);
}

// ====================================================================
// Kernel 0: split X and Wx (concat) into bf16 hi/lo; build bias concat.
// ====================================================================
#define NX4 ((size_t)T_STEPS * B_SZ * D_SZ / 4)      // 4,194,304
#define NW4 ((size_t)D_SZ * G4 / 4)                  // 524,288

__global__ void __launch_bounds__(256) conv_prep(
    const float* __restrict__ X,
    const float* __restrict__ Wx0, const float* __restrict__ Wx1,
    const float* __restrict__ Wx2, const float* __restrict__ Wx3,
    const float* __restrict__ b0p, const float* __restrict__ b1p,
    const float* __restrict__ b2p, const float* __restrict__ b3p)
{
    size_t i = (size_t)blockIdx.x * 256 + threadIdx.x;
    if (i < NX4) {
        float4 v = ((const float4*)X)[i];
        unsigned h0, h1, h2, h3, l0, l1, l2, l3;
        split2u(v.x, h0, l0); split2u(v.y, h1, l1);
        split2u(v.z, h2, l2); split2u(v.w, h3, l3);
        *(uint2*)&g_Xh[i * 4] = make_uint2(h0 | (h1 << 16), h2 | (h3 << 16));
        *(uint2*)&g_Xl[i * 4] = make_uint2(l0 | (l1 << 16), l2 | (l3 << 16));
    } else if (i < NX4 + NW4) {
        size_t d = i - NX4;
        int k  = (int)(d >> 10);
        int c4 = (int)(d & 1023);
        int col  = c4 * 4;
        int gate = col >> 10;
        int n    = col & 1023;
        const float* W = (gate == 0) ? Wx0 : (gate == 1) ? Wx1 : (gate == 2) ? Wx2 : Wx3;
        float4 v = *(const float4*)&W[(size_t)k * 1024 + n];
        unsigned h0, h1, h2, h3, l0, l1, l2, l3;
        split2u(v.x, h0, l0); split2u(v.y, h1, l1);
        split2u(v.z, h2, l2); split2u(v.w, h3, l3);
        *(uint2*)&g_Wxh[d * 4] = make_uint2(h0 | (h1 << 16), h2 | (h3 << 16));
        *(uint2*)&g_Wxl[d * 4] = make_uint2(l0 | (l1 << 16), l2 | (l3 << 16));
    }
    if (i < G4 / 4) {
        int col = (int)i * 4;
        int gate = col >> 10, n = col & 1023;
        const float* bg = (gate == 0) ? b0p : (gate == 1) ? b1p : (gate == 2) ? b2p : b3p;
        ((float4*)g_bcat)[i] = *(const float4*)&bg[n];
    }
}

// ====================================================================
// Kernel 1: Xg = X @ Wxcat + bcat via split-bf16 3-pass mma.sync.
// (unchanged from passing R7 version)
// ====================================================================
#define XA_HI(buf) ((buf)*36864)                   // [128][72] bf16
#define XA_LO(buf) ((buf)*36864 + 18432)
#define XB_HI(buf) (73728 + (buf)*34816)           // [64][136] bf16
#define XB_LO(buf) (73728 + (buf)*34816 + 17408)
#define XG_SMEM    143360

__global__ void __launch_bounds__(256, 1) xg_mma()
{
    extern __shared__ char smc[];
    const uint32_t smem_base = smem_u32(smc);
    const int tid  = threadIdx.x;
    const int wid  = tid >> 5;
    const int lane = tid & 31;
    const int m0   = blockIdx.y * 128;
    const int nb   = blockIdx.x * 128;
    const int mw   = (wid & 3) * 32;
    const int nw   = (wid >> 2) * 64;

    const int arow = ((lane >> 3) & 1) * 8 + (lane & 7);
    const int acol = (lane >> 4) * 8;
    const int brow = ((lane >> 3) & 1) * 8 + (lane & 7);
    const int bcol = (lane >> 4) * 8;

    float acc[2][8][4];
    #pragma unroll
    for (int m = 0; m < 2; ++m)
        #pragma unroll
        for (int n = 0; n < 8; ++n)
            #pragma unroll
            for (int q = 0; q < 4; ++q) acc[m][n][q] = 0.f;

    auto issue_chunk = [&](int s, int buf) {
        #pragma unroll
        for (int i = 0; i < 4; ++i) {
            int idx = tid + i * 256;
            int row = idx >> 3, c8 = (idx & 7) * 8;
            uint32_t sa = smem_base + XA_HI(buf) + (uint32_t)(row * 72 + c8) * 2u;
            size_t go = (size_t)(m0 + row) * D_SZ + s * 64 + c8;
            cp16(sa,          g_Xh + go);
            cp16(sa + 18432u, g_Xl + go);
        }
        #pragma unroll
        for (int i = 0; i < 4; ++i) {
            int idx = tid + i * 256;
            int r = idx >> 4, c8 = (idx & 15) * 8;
            uint32_t sb = smem_base + XB_HI(buf) + (uint32_t)(r * 136 + c8) * 2u;
            size_t go = (size_t)(s * 64 + r) * G4 + nb + c8;
            cp16(sb,          g_Wxh + go);
            cp16(sb + 17408u, g_Wxl + go);
        }
        CP_COMMIT();
    };

    issue_chunk(0, 0);
    #pragma unroll 1
    for (int s = 0; s < 8; ++s) {
        if (s < 7) { issue_chunk(s + 1, (s + 1) & 1); CP_WAIT(1); }
        else       { CP_WAIT(0); }
        __syncthreads();

        const int buf = s & 1;
        const uint32_t Ah = smem_base + XA_HI(buf);
        const uint32_t Bh = smem_base + XB_HI(buf);
        #pragma unroll
        for (int kt = 0; kt < 4; ++kt) {
            uint32_t ah[2][4], al[2][4];
            #pragma unroll
            for (int m = 0; m < 2; ++m) {
                uint32_t ar = Ah + (uint32_t)((mw + m * 16 + arow) * 72 + kt * 16 + acol) * 2u;
                ldsm_x4(ah[m], ar);
                ldsm_x4(al[m], ar + 18432u);
            }
            uint32_t bh[4][4], bl[4][4];
            #pragma unroll
            for (int np = 0; np < 4; ++np) {
                uint32_t br = Bh + (uint32_t)((kt * 16 + brow) * 136 + nw + np * 16 + bcol) * 2u;
                ldsm_x4t(bh[np], br);
                ldsm_x4t(bl[np], br + 17408u);
            }
            #pragma unroll
            for (int m = 0; m < 2; ++m)
                #pragma unroll
                for (int np = 0; np < 4; ++np) {
                    mma16816(acc[m][2*np],   ah[m], bh[np][0], bh[np][1]);
                    mma16816(acc[m][2*np],   ah[m], bl[np][0], bl[np][1]);
                    mma16816(acc[m][2*np],   al[m], bh[np][0], bh[np][1]);
                    mma16816(acc[m][2*np+1], ah[m], bh[np][2], bh[np][3]);
                    mma16816(acc[m][2*np+1], ah[m], bl[np][2], bl[np][3]);
                    mma16816(acc[m][2*np+1], al[m], bh[np][2], bh[np][3]);
                }
        }
        __syncthreads();
    }

    const int r0    = m0 + mw + (lane >> 2);
    const int cbase = nb + nw + (lane & 3) * 2;
    #pragma unroll
    for (int m = 0; m < 2; ++m) {
        #pragma unroll
        for (int nt = 0; nt < 8; ++nt) {
            int col = cbase + nt * 8;
            float b0 = g_bcat[col], b1 = g_bcat[col + 1];
            int rr = r0 + m * 16;
            float* p0 = g_xg + (size_t)rr * G4 + col;
            float* p1 = g_xg + (size_t)(rr + 8) * G4 + col;
            *(float2*)p0 = make_float2(acc[m][nt][0] + b0, acc[m][nt][1] + b1);
            *(float2*)p1 = make_float2(acc[m][nt][2] + b0, acc[m][nt][3] + b1);
        }
    }
}

// ====================================================================
// Kernel 2: persistent mma.sync recurrence v3.
// - cp.async 3-deep pipeline for H staging (3 A buffers, issue s+2 while
//   computing s; issue AFTER the chunk sync so buffer reuse is race-free).
// - Epilogue spread over all 256 threads (2 h-elems/thread, C in 2 regs).
// - Xg prefetched into registers at step start (no SMEM tile).
// - 1 flag increment/step (need = t); fp32 out stores after the flag.
// ====================================================================

#define RM_W_HI 0                      // 1024 x 40 bf16 = 81920
#define RM_W_LO 81920
#define RM_A    163840                 // 3 bufs x {hi,lo} x 64x72 bf16 (18432 ea)
#define RM_G    219136                 // 64x33 f32 = 8448
#define RM_TOTAL 227584

__global__ void __launch_bounds__(256, 1) lstm_rec(
    const float* __restrict__ Wh0, const float* __restrict__ Wh1,
    const float* __restrict__ Wh2, const float* __restrict__ Wh3,
    float* __restrict__ out, int out_size)
{
    extern __shared__ char smc[];
    const uint32_t smem_base = smem_u32(smc);
    const int tid  = threadIdx.x;
    const int wid  = tid >> 5;
    const int lane = tid & 31;
    const int h0   = blockIdx.x * 8;

    if (tid == 0) g_ready[blockIdx.x] = 0;

    // ---- fill resident Wh slice: [k][n=gate*8+hh], stride 40, hi+lo ----
    {
        __nv_bfloat16* wh = (__nv_bfloat16*)(smc + RM_W_HI);
        __nv_bfloat16* wl = (__nv_bfloat16*)(smc + RM_W_LO);
        for (int i = tid; i < 32 * 1024; i += 256) {
            int k = i >> 5, n = i & 31;
            int gate = n >> 3;
            const float* W = (gate == 0) ? Wh0 : (gate == 1) ? Wh1
                             : (gate == 2) ? Wh2 : Wh3;
            float w = W[(size_t)k * H_SZ + h0 + (n & 7)];
            __nv_bfloat16 hi = __float2bfloat16(w);
            __nv_bfloat16 lo = __float2bfloat16(w - __bfloat162float(hi));
            wh[k * 40 + n] = hi;
            wl[k * 40 + n] = lo;
        }
    }
    init_barrier();   // flags reset visible; Wh fill synced

    // ---- warp tile geometry (MMA) ----
    const int mt    = wid & 3;
    const int npair = wid >> 2;
    const int arow  = mt * 16 + (((lane >> 3) & 1) << 3) + (lane & 7);
    const int acol  = (lane >> 4) << 3;
    const uint32_t a_off = (uint32_t)(arow * 72 + acol) * 2u;
    const int brow  = (((lane >> 3) & 1) << 3) + (lane & 7);
    const int bcol  = npair * 16 + ((lane >> 4) << 3);
    const uint32_t b_lane = (uint32_t)(brow * 40 + bcol) * 2u;
    const uint32_t b_hi_base = smem_base + RM_W_HI + b_lane;
    const uint32_t b_lo_base = smem_base + RM_W_LO + b_lane;

    // staging lane mapping (constant): two 16B rows per thread
    const int lr0 = tid >> 3,          lc0 = (tid & 7) * 8;
    const int lr1 = (tid + 256) >> 3,  lc1 = lc0;          // same fc columns
    const uint32_t so0 = (uint32_t)(lr0 * 72 + lc0) * 2u;
    const uint32_t so1 = (uint32_t)(lr1 * 72 + lc1) * 2u;
    const int fc = tid & 7;           // producer index within a chunk

    // epilogue mapping: thread -> (batch row b2, h pair hq)
    const int b2 = tid >> 2;
    const int hq = (tid & 3) * 2;
    const size_t hidx = (size_t)b2 * H_SZ + h0 + hq;

    float c0 = 0.f, c1 = 0.f;
    float* sG = (float*)(smc + RM_G);

    for (int t = 0; t < T_STEPS; ++t) {
        // ---- Xg prefetch into registers (consumed in epilogue) ----
        const float* xb = g_xg + ((size_t)t * B_SZ + b2) * G4 + h0 + hq;
        float2 xv0 = __ldcg((const float2*)xb);
        float2 xv1 = __ldcg((const float2*)(xb + 1024));
        float2 xv2 = __ldcg((const float2*)(xb + 2048));
        float2 xv3 = __ldcg((const float2*)(xb + 3072));

        float acc0[4] = {0.f, 0.f, 0.f, 0.f};
        float acc1[4] = {0.f, 0.f, 0.f, 0.f};

        if (t > 0) {
            const int rb = (t - 1) & 1;
            const __nv_bfloat16* Hh = g_Hh[rb];
            const __nv_bfloat16* Hl = g_Hl[rb];
            const int need = t;

            // cp.async issue for chunk s into buf s%3
            auto issue_cp = [&](int s) {
                const uint32_t ab = smem_base + RM_A + (uint32_t)(s % 3) * 18432u;
                const size_t k0 = (size_t)s * 64;
                cp16(ab + so0,         Hh + (size_t)lr0 * H_SZ + k0 + lc0);
                cp16(ab + 9216u + so0, Hl + (size_t)lr0 * H_SZ + k0 + lc0);
                cp16(ab + so1,         Hh + (size_t)lr1 * H_SZ + k0 + lc1);
                cp16(ab + 9216u + so1, Hl + (size_t)lr1 * H_SZ + k0 + lc1);
                CP_COMMIT();
            };

            // pre-loop: chunks 0 and 1
            int fv = __ldcg(&g_ready[fc]);
            if (fv < need) wait_ready(fc, need);
            issue_cp(0);
            fv = __ldcg(&g_ready[8 + fc]);
            if (fv < need) wait_ready(8 + fc, need);
            issue_cp(1);
            fv = __ldcg(&g_ready[16 + fc]);   // chunk 2 flag, early

            #pragma unroll 1
            for (int s = 0; s < 16; ++s) {
                if (s < 15) CP_WAIT(1); else CP_WAIT(0);
                __syncthreads();   // chunk s data visible; all warps done ldsm s-1

                if (s < 14) {
                    if (fv < need) wait_ready((s + 2) * 8 + fc, need);
                    issue_cp(s + 2);
                    if (s < 13) fv = __ldcg(&g_ready[(s + 3) * 8 + fc]);
                }

                const uint32_t a_hi = smem_base + RM_A + (uint32_t)(s % 3) * 18432u + a_off;
                const uint32_t a_lo = a_hi + 9216u;
                const uint32_t boff = (uint32_t)s * 5120u;   // s*64 k-rows * 80B
                #pragma unroll
                for (int kt = 0; kt < 4; ++kt) {
                    uint32_t ah[4], al[4], bh[4], bl[4];
                    ldsm_x4 (ah, a_hi + kt * 32);
                    ldsm_x4 (al, a_lo + kt * 32);
                    ldsm_x4t(bh, b_hi_base + boff + kt * 1280);
                    ldsm_x4t(bl, b_lo_base + boff + kt * 1280);
                    mma16816(acc0, ah, bh[0], bh[1]);
                    mma16816(acc0, ah, bl[0], bl[1]);
                    mma16816(acc0, al, bh[0], bh[1]);
                    mma16816(acc1, ah, bh[2], bh[3]);
                    mma16816(acc1, ah, bl[2], bl[3]);
                    mma16816(acc1, al, bh[2], bh[3]);
                }
            }

            // store fragments to sG [64][33]
            {
                int r0  = mt * 16 + (lane >> 2);
                int col = npair * 16 + (lane & 3) * 2;
                sG[r0 * 33 + col]           = acc0[0];
                sG[r0 * 33 + col + 1]       = acc0[1];
                sG[(r0 + 8) * 33 + col]     = acc0[2];
                sG[(r0 + 8) * 33 + col + 1] = acc0[3];
                sG[r0 * 33 + col + 8]           = acc1[0];
                sG[r0 * 33 + col + 9]           = acc1[1];
                sG[(r0 + 8) * 33 + col + 8]     = acc1[2];
                sG[(r0 + 8) * 33 + col + 9]     = acc1[3];
            }
        }
        __syncthreads();   // sG visible to everyone

        // ---- epilogue: all 256 threads, 2 h-elements each ----
        float gi0, gf0, go0, gc0, gi1, gf1, go1, gc1;
        if (t > 0) {
            const float* gr = sG + b2 * 33;
            gi0 = gr[hq]      + xv0.x;  gi1 = gr[hq + 1]      + xv0.y;
            gf0 = gr[8 + hq]  + xv1.x;  gf1 = gr[8 + hq + 1]  + xv1.y;
            go0 = gr[16 + hq] + xv2.x;  go1 = gr[16 + hq + 1] + xv2.y;
            gc0 = gr[24 + hq] + xv3.x;  gc1 = gr[24 + hq + 1] + xv3.y;
        } else {
            gi0 = xv0.x; gi1 = xv0.y; gf0 = xv1.x; gf1 = xv1.y;
            go0 = xv2.x; go1 = xv2.y; gc0 = xv3.x; gc1 = xv3.y;
        }

        float Iv = __fdividef(1.f, 1.f + __expf(-gi0));
        float Fv = __fdividef(1.f, 1.f + __expf(-gf0));
        float Ov = __fdividef(1.f, 1.f + __expf(-go0));
        float Ct = 1.f - __fdividef(2.f, __expf(2.f * gc0) + 1.f);
        c0 = Fv * c0 + Iv * Ct;
        float Hn0 = Ov * (1.f - __fdividef(2.f, __expf(2.f * c0) + 1.f));

        Iv = __fdividef(1.f, 1.f + __expf(-gi1));
        Fv = __fdividef(1.f, 1.f + __expf(-gf1));
        Ov = __fdividef(1.f, 1.f + __expf(-go1));
        Ct = 1.f - __fdividef(2.f, __expf(2.f * gc1) + 1.f);
        c1 = Fv * c1 + Iv * Ct;
        float Hn1 = Ov * (1.f - __fdividef(2.f, __expf(2.f * c1) + 1.f));

        // publish split-bf16 H (consumers' data) FIRST
        {
            const int wb = t & 1;
            __nv_bfloat16 h0b = __float2bfloat16(Hn0);
            __nv_bfloat16 h1b = __float2bfloat16(Hn1);
            __nv_bfloat16 l0b = __float2bfloat16(Hn0 - __bfloat162float(h0b));
            __nv_bfloat16 l1b = __float2bfloat16(Hn1 - __bfloat162float(h1b));
            unsigned hp = (unsigned)*(unsigned short*)&h0b
                        | ((unsigned)*(unsigned short*)&h1b << 16);
            unsigned lp = (unsigned)*(unsigned short*)&l0b
                        | ((unsigned)*(unsigned short*)&l1b << 16);
            *(unsigned*)&g_Hh[wb][hidx] = hp;
            *(unsigned*)&g_Hl[wb][hidx] = lp;
        }
        __threadfence();   // release H writes (per-thread)
        __syncthreads();   // all threads' H published
        if (tid == 0) atomicAdd(&g_ready[blockIdx.x], 1);

        // fp32 outputs AFTER the flag (off the recurrence critical path)
        *(float2*)&out[(size_t)t * BH + hidx] = make_float2(Hn0, Hn1);
        if (t == T_STEPS - 1) {
            size_t base = (size_t)T_STEPS * BH;
            if ((size_t)out_size >= base + (size_t)BH)
                *(float2*)&out[base + hidx] = make_float2(Hn0, Hn1);
            if ((size_t)out_size >= base + 2 * (size_t)BH)
                *(float2*)&out[base + BH + hidx] = make_float2(c0, c1);
        }
    }
}

// ====================================================================
// launch
// ====================================================================
extern "C" void kernel_launch(void* const* d_in, const int* in_sizes, int n_in,
                              void* d_out, int out_size) {
    const float* X   = (const float*)d_in[0];
    const float* Wxi = (const float*)d_in[1];
    const float* Whi = (const float*)d_in[2];
    const float* bi  = (const float*)d_in[3];
    const float* Wxf = (const float*)d_in[4];
    const float* Whf = (const float*)d_in[5];
    const float* bf  = (const float*)d_in[6];
    const float* Wxo = (const float*)d_in[7];
    const float* Who = (const float*)d_in[8];
    const float* bo  = (const float*)d_in[9];
    const float* Wxc = (const float*)d_in[10];
    const float* Whc = (const float*)d_in[11];
    const float* bc  = (const float*)d_in[12];
    float* out = (float*)d_out;

    // Phase 0: split X / Wx into bf16 hi/lo, build bias concat
    int cblocks = (int)((NX4 + NW4) / 256);
    conv_prep<<<cblocks, 256>>>(X, Wxi, Wxf, Wxo, Wxc, bi, bf, bo, bc);

    // Phase 1: Xg = X @ Wxcat + b via tensor cores
    cudaFuncSetAttribute(xg_mma, cudaFuncAttributeMaxDynamicSharedMemorySize,
                         XG_SMEM);
    xg_mma<<<dim3(32, 256), 256, XG_SMEM>>>();

    // Phase 2: persistent recurrence with wavefront flags
    cudaFuncSetAttribute(lstm_rec, cudaFuncAttributeMaxDynamicSharedMemorySize,
                         RM_TOTAL);
    lstm_rec<<<NCTA, 256, RM_TOTAL>>>(Whi, Whf, Who, Whc, out, out_size);
}